// round 12
// baseline (speedup 1.0000x reference)
#include <cuda_runtime.h>
#include <cuda_bf16.h>
#include <cstdint>

#define MAXN 200704
#define MAXE 1250048
__device__ float g_agg[(size_t)MAXN * 192];
__device__ float g_h1[(size_t)MAXN * 128];
__device__ int   g_degi[MAXN];
__device__ int   g_rowptr[MAXN + 8];
__device__ int   g_cur[MAXN];
__device__ int   g_csr[MAXE];
__device__ int   g_bsum[1032];
__device__ float g_w2p[32768];     // folded W2l' then W2r'
__device__ float g_uv[256];        // u = t@W2l ; v = t@W2r
__device__ float g_stats[16384];   // layer L at L*8192: [sum 128x32][sq 128x32]
__device__ float g_scale[128];
__device__ float g_shift[128];

// ---------------------------------------------------------------------------
__device__ __forceinline__ void red_add1(float* p, float v) {
    asm volatile("red.global.add.f32 [%0], %1;" :: "l"(p), "f"(v) : "memory");
}
__device__ __forceinline__ void mma_bf16(float* d, const uint32_t* a,
                                         uint32_t b0, uint32_t b1) {
    asm volatile("mma.sync.aligned.m16n8k16.row.col.f32.bf16.bf16.f32 "
                 "{%0,%1,%2,%3},{%4,%5,%6,%7},{%8,%9},{%0,%1,%2,%3};"
                 : "+f"(d[0]), "+f"(d[1]), "+f"(d[2]), "+f"(d[3])
                 : "r"(a[0]), "r"(a[1]), "r"(a[2]), "r"(a[3]),
                   "r"(b0), "r"(b1));
}
// split (x,y) into packed bf16 hi pair (ret) and lo pair (out param)
__device__ __forceinline__ uint32_t bfsplit2(float x, float y, uint32_t& lo2) {
    __nv_bfloat16 hx = __float2bfloat16(x);
    __nv_bfloat16 hy = __float2bfloat16(y);
    __nv_bfloat16 lx = __float2bfloat16(x - __bfloat162float(hx));
    __nv_bfloat16 ly = __float2bfloat16(y - __bfloat162float(hy));
    lo2 = (uint32_t)__bfloat16_as_ushort(lx) | ((uint32_t)__bfloat16_as_ushort(ly) << 16);
    return (uint32_t)__bfloat16_as_ushort(hx) | ((uint32_t)__bfloat16_as_ushort(hy) << 16);
}

// ---------------------------------------------------------------------------
// CSR build: histogram -> 3-step exclusive scan -> bucket fill
// ---------------------------------------------------------------------------
__global__ void csr_hist(const int* __restrict__ ei, int E, int* __restrict__ degi) {
    int e = blockIdx.x * blockDim.x + threadIdx.x;
    if (e >= E) return;
    atomicAdd(&degi[ei[E + e]], 1);
}
__global__ void scanA(const int* __restrict__ degi, int n,
                      int* __restrict__ locex, int* __restrict__ bsum) {
    int i = blockIdx.x * 256 + threadIdx.x;
    int v = (i < n) ? degi[i] : 0;
    int lane = threadIdx.x & 31, w = threadIdx.x >> 5;
    int x = v;
#pragma unroll
    for (int o = 1; o < 32; o <<= 1) {
        int t = __shfl_up_sync(0xFFFFFFFFu, x, o);
        if (lane >= o) x += t;
    }
    __shared__ int ws[8], wp[8];
    if (lane == 31) ws[w] = x;
    __syncthreads();
    if (threadIdx.x == 0) {
        int run = 0;
#pragma unroll
        for (int j = 0; j < 8; j++) { wp[j] = run; run += ws[j]; }
        bsum[blockIdx.x] = run;
    }
    __syncthreads();
    if (i < MAXN) locex[i] = x - v + wp[w];
}
__global__ void scanB(int* __restrict__ bsum, int nb) {
    __shared__ int s[1024];
    int t = threadIdx.x;
    int v = (t < nb) ? bsum[t] : 0;
    s[t] = v;
    __syncthreads();
    for (int o = 1; o < 1024; o <<= 1) {
        int add = (t >= o) ? s[t - o] : 0;
        __syncthreads();
        s[t] += add;
        __syncthreads();
    }
    if (t < nb) bsum[t] = s[t] - v;
}
__global__ void scanC(const int* __restrict__ locex, const int* __restrict__ bsum,
                      int n, int E, int* __restrict__ rowptr, int* __restrict__ cur) {
    int i = blockIdx.x * 256 + threadIdx.x;
    if (i < n) {
        int r = locex[i] + bsum[blockIdx.x];
        rowptr[i] = r;
        cur[i] = r;
    }
    if (i == 0) rowptr[n] = E;
}
__global__ void csr_fill(const int* __restrict__ ei, int E,
                         int* __restrict__ cur, int* __restrict__ csr) {
    int e = blockIdx.x * blockDim.x + threadIdx.x;
    if (e >= E) return;
    int s = ei[e], d = ei[E + e];
    int pos = atomicAdd(&cur[d], 1);
    csr[pos] = s;
}

// ---------------------------------------------------------------------------
// Gather aggregation: one warp per dst node, feature-half passes.
// ---------------------------------------------------------------------------
template <int F>
__global__ void sage_gather(const float* __restrict__ feat,
                            const int* __restrict__ rowptr,
                            const int* __restrict__ csr,
                            float* __restrict__ agg, int n, int f_lo) {
    constexpr int LPE = F / 8;
    constexpr int EP  = 32 / LPE;
    int gw = (blockIdx.x * blockDim.x + threadIdx.x) >> 5;
    if (gw >= n) return;
    int lane  = threadIdx.x & 31;
    int eslot = lane / LPE;
    int fo    = f_lo + (lane % LPE) * 4;
    int b = rowptr[gw], e = rowptr[gw + 1];
    float4 acc = make_float4(0.f, 0.f, 0.f, 0.f);
    for (int i = b + eslot; i < e; i += EP) {
        int s = csr[i];
        float4 v = *(const float4*)(feat + (size_t)s * F + fo);
        acc.x += v.x; acc.y += v.y; acc.z += v.z; acc.w += v.w;
    }
#pragma unroll
    for (int o = LPE; o < 32; o <<= 1) {
        acc.x += __shfl_down_sync(0xFFFFFFFFu, acc.x, o);
        acc.y += __shfl_down_sync(0xFFFFFFFFu, acc.y, o);
        acc.z += __shfl_down_sync(0xFFFFFFFFu, acc.z, o);
        acc.w += __shfl_down_sync(0xFFFFFFFFu, acc.w, o);
    }
    if (eslot == 0)
        *(float4*)(agg + (size_t)gw * F + fo) = acc;
}

// Fold BN1 into layer-2 weights
__global__ void prep_layer2(const float* __restrict__ W2l,
                            const float* __restrict__ W2r,
                            float* __restrict__ W2lp, float* __restrict__ W2rp,
                            float* __restrict__ uv) {
    int nidx = threadIdx.x & 127;
    int ko   = threadIdx.x >> 7;
    int kb   = blockIdx.x * 8;
    float usum = 0.f, vsum = 0.f;
#pragma unroll
    for (int i = 0; i < 4; i++) {
        int k = kb + i * 2 + ko;
        float s = g_scale[k], t = g_shift[k];
        float wl = W2l[k * 128 + nidx];
        float wr = W2r[k * 128 + nidx];
        W2lp[k * 128 + nidx] = wl * s;
        W2rp[k * 128 + nidx] = wr * s;
        usum += t * wl;
        vsum += t * wr;
    }
    red_add1(&uv[nidx], usum);
    red_add1(&uv[128 + nidx], vsum);
}

// ---------------------------------------------------------------------------
// Persistent tensor-core dual GEMM: mma.sync m16n8k16 bf16, 3-term split.
// Fragments via plain LDS with hi/lo INTERLEAVED as uint2 -> one LDS.64
// fetches both precision halves (R12 change). A rows stride 20 uint2, W rows
// K/2+4 uint2 -> bank = (8g+2t) mod 32 permutation, conflict-free LDS.64.
// ---------------------------------------------------------------------------
template <int K, bool DEG>
__global__ void __launch_bounds__(512, 1)
sage_gemm_tc(const float* __restrict__ A1,
             const float* __restrict__ A2,
             const float* __restrict__ Wl,
             const float* __restrict__ Wr,
             const float* __restrict__ bias,
             const float* __restrict__ uv,
             const int* __restrict__ degi,
             float* __restrict__ out, float* __restrict__ stats,
             int n, int ntiles) {
    extern __shared__ char smx[];
    constexpr int Kh  = K / 2;
    constexpr int NCH = K / 32;              // 32-k chunks
    constexpr int WW2 = K / 2 + 4;           // W row stride in uint2 (≡4 mod 16)
    constexpr int AW2 = 128 * 20;            // uint2 per A buffer (row stride 20)
    uint2* sW = (uint2*)smx;                 // [128][WW2] {hi,lo}
    uint2* sA = sW + 128 * WW2;              // 2 bufs x [128][20] {hi,lo}

    const int tid    = threadIdx.x;
    const int lane   = tid & 31;
    const int wid    = tid >> 5;
    const int warp_m = wid & 3;
    const int warp_n = wid >> 2;
    const int g      = lane >> 2;    // group 0..7
    const int t      = lane & 3;     // thread-in-group 0..3

    // ---- pack weights: per k-pair, interleaved {hi,lo}, transposed [n][kp] ----
    for (int i = tid; i < 128 * (Kh / 2); i += 512) {
        int kp = i >> 7, nn = i & 127;
        float w0 = Wl[(2 * kp) * 128 + nn];
        float w1 = Wl[(2 * kp + 1) * 128 + nn];
        uint32_t lo, hi = bfsplit2(w0, w1, lo);
        sW[nn * WW2 + kp] = make_uint2(hi, lo);
        w0 = Wr[(2 * kp) * 128 + nn];
        w1 = Wr[(2 * kp + 1) * 128 + nn];
        hi = bfsplit2(w0, w1, lo);
        sW[nn * WW2 + Kh / 2 + kp] = make_uint2(hi, lo);
    }

    // epilogue constants: thread owns cols 32*warp_n + 8*ni + 2*t + j
    float bs[8], us[8];
#pragma unroll
    for (int ni = 0; ni < 4; ni++) {
#pragma unroll
        for (int j = 0; j < 2; j++) {
            int c = 32 * warp_n + 8 * ni + 2 * t + j;
            if (DEG) { bs[ni * 2 + j] = bias[c] + uv[128 + c]; us[ni * 2 + j] = uv[c]; }
            else     { bs[ni * 2 + j] = bias[c]; us[ni * 2 + j] = 0.f; }
        }
    }
    __syncthreads();

    // staging mapping: thread -> row tid>>2, k-seg (tid&3)*8 (8 floats = 4 pairs)
    const int srow = tid >> 2;
    const int spair = (tid & 3) * 4;         // first k-pair index in row

    for (int tile = blockIdx.x; tile < ntiles; tile += gridDim.x) {
        const int row0 = tile << 7;

        // ---- stage chunk 0 ----
        {
            int gr = row0 + srow;
            float4 v0 = make_float4(0.f,0.f,0.f,0.f), v1 = v0;
            if (gr < n) {
                v0 = *(const float4*)(A1 + (size_t)gr * Kh + spair * 2);
                v1 = *(const float4*)(A1 + (size_t)gr * Kh + spair * 2 + 4);
            }
            uint4 I0, I1;   // interleaved {hi,lo,hi,lo}
            I0.x = bfsplit2(v0.x, v0.y, I0.y);
            I0.z = bfsplit2(v0.z, v0.w, I0.w);
            I1.x = bfsplit2(v1.x, v1.y, I1.y);
            I1.z = bfsplit2(v1.z, v1.w, I1.w);
            *(uint4*)(sA + srow * 20 + spair)     = I0;
            *(uint4*)(sA + srow * 20 + spair + 2) = I1;
        }
        __syncthreads();

        float acc[2][4][4];
#pragma unroll
        for (int mi = 0; mi < 2; mi++)
#pragma unroll
            for (int ni = 0; ni < 4; ni++)
#pragma unroll
                for (int q = 0; q < 4; q++) acc[mi][ni][q] = 0.f;

        for (int c = 0; c < NCH; c++) {
            const int b = c & 1;
            float4 p0, p1;
            const bool havnext = (c + 1 < NCH);
            if (havnext) {
                const int kg0 = (c + 1) * 32;
                const float* src = (kg0 < Kh) ? A1 : A2;
                const int kof = kg0 & (Kh - 1);
                int gr = row0 + srow;
                p0 = make_float4(0.f,0.f,0.f,0.f); p1 = p0;
                if (gr < n) {
                    p0 = *(const float4*)(src + (size_t)gr * Kh + kof + spair * 2);
                    p1 = *(const float4*)(src + (size_t)gr * Kh + kof + spair * 2 + 4);
                }
            }

            // ---- MMA over chunk c: 2 k16-steps ----
            const uint2* sAb = sA + b * AW2;
#pragma unroll
            for (int ks = 0; ks < 2; ks++) {
                const int kw = c * 16 + ks * 8;   // k-pair offset in W rows
                const int aw = ks * 8;            // k-pair offset in A rows
                // B fragments: one LDS.64 each = {hi,lo}
                uint2 qb0[4], qb1[4];
#pragma unroll
                for (int ni = 0; ni < 4; ni++) {
                    int nb = 32 * warp_n + 8 * ni + g;
                    qb0[ni] = sW[nb * WW2 + kw + t];
                    qb1[ni] = sW[nb * WW2 + kw + t + 4];
                }
#pragma unroll
                for (int mi = 0; mi < 2; mi++) {
                    const int rb = (32 * warp_m + 16 * mi + g) * 20 + aw + t;
                    uint2 pa0 = sAb[rb];
                    uint2 pa1 = sAb[rb + 8 * 20];
                    uint2 pa2 = sAb[rb + 4];
                    uint2 pa3 = sAb[rb + 8 * 20 + 4];
                    uint32_t ah[4] = { pa0.x, pa1.x, pa2.x, pa3.x };
                    uint32_t al[4] = { pa0.y, pa1.y, pa2.y, pa3.y };
#pragma unroll
                    for (int ni = 0; ni < 4; ni++) {
                        mma_bf16(acc[mi][ni], ah, qb0[ni].x, qb1[ni].x);
                        mma_bf16(acc[mi][ni], al, qb0[ni].x, qb1[ni].x);
                        mma_bf16(acc[mi][ni], ah, qb0[ni].y, qb1[ni].y);
                    }
                }
            }

            if (havnext) {
                const int bn = (c + 1) & 1;
                uint4 I0, I1;
                I0.x = bfsplit2(p0.x, p0.y, I0.y);
                I0.z = bfsplit2(p0.z, p0.w, I0.w);
                I1.x = bfsplit2(p1.x, p1.y, I1.y);
                I1.z = bfsplit2(p1.z, p1.w, I1.w);
                *(uint4*)(sA + bn * AW2 + srow * 20 + spair)     = I0;
                *(uint4*)(sA + bn * AW2 + srow * 20 + spair + 2) = I1;
            }
            __syncthreads();
        }

        // ---- epilogue: bias(+deg*u), relu, store, BN stats ----
        float psum[8], psq[8];
#pragma unroll
        for (int q = 0; q < 8; q++) { psum[q] = 0.f; psq[q] = 0.f; }

#pragma unroll
        for (int mi = 0; mi < 2; mi++) {
#pragma unroll
            for (int half = 0; half < 2; half++) {
                int gr = row0 + 32 * warp_m + 16 * mi + g + 8 * half;
                if (gr >= n) continue;
                float dg = DEG ? (float)degi[gr] : 0.f;
#pragma unroll
                for (int ni = 0; ni < 4; ni++) {
                    int c0 = 32 * warp_n + 8 * ni + 2 * t;
                    float v0 = acc[mi][ni][2 * half]     + bs[ni * 2]     + dg * us[ni * 2];
                    float v1 = acc[mi][ni][2 * half + 1] + bs[ni * 2 + 1] + dg * us[ni * 2 + 1];
                    v0 = fmaxf(v0, 0.f);
                    v1 = fmaxf(v1, 0.f);
                    psum[ni * 2]     += v0;  psq[ni * 2]     += v0 * v0;
                    psum[ni * 2 + 1] += v1;  psq[ni * 2 + 1] += v1 * v1;
                    *(float2*)(out + (size_t)gr * 128 + c0) = make_float2(v0, v1);
                }
            }
        }
#pragma unroll
        for (int q = 0; q < 8; q++) {
#pragma unroll
            for (int o = 4; o < 32; o <<= 1) {
                psum[q] += __shfl_down_sync(0xFFFFFFFFu, psum[q], o);
                psq[q]  += __shfl_down_sync(0xFFFFFFFFu, psq[q], o);
            }
        }
        if (g == 0) {
            int slot = ((tile & 7) << 2) | warp_m;
#pragma unroll
            for (int q = 0; q < 8; q++) {
                int col = 32 * warp_n + 8 * (q >> 1) + 2 * t + (q & 1);
                red_add1(&stats[col * 32 + slot], psum[q]);
                red_add1(&stats[4096 + col * 32 + slot], psq[q]);
            }
        }
        __syncthreads();
    }
}

// ---------------------------------------------------------------------------
__global__ void bn_finalize(const float* __restrict__ gamma,
                            const float* __restrict__ beta,
                            const float* __restrict__ stats, float inv_n) {
    int c = threadIdx.x;
    float s = 0.f, q = 0.f;
#pragma unroll
    for (int j = 0; j < 32; j++) {
        s += stats[c * 32 + j];
        q += stats[4096 + c * 32 + j];
    }
    float mu  = s * inv_n;
    float var = q * inv_n - mu * mu;
    float sc  = gamma[c] * rsqrtf(var + 1e-5f);
    g_scale[c] = sc;
    g_shift[c] = beta[c] - mu * sc;
}

__global__ void bn_apply_relu(float* __restrict__ out, int total4) {
    int i = blockIdx.x * blockDim.x + threadIdx.x;
    if (i >= total4) return;
    float4 v = ((float4*)out)[i];
    int c = (i & 31) * 4;
    float4 sc = *(const float4*)(g_scale + c);
    float4 sh = *(const float4*)(g_shift + c);
    v.x = fmaxf(fmaf(v.x, sc.x, sh.x), 0.f);
    v.y = fmaxf(fmaf(v.y, sc.y, sh.y), 0.f);
    v.z = fmaxf(fmaf(v.z, sc.z, sh.z), 0.f);
    v.w = fmaxf(fmaf(v.w, sc.w, sh.w), 0.f);
    ((float4*)out)[i] = v;
}

// ---------------------------------------------------------------------------
extern "C" void kernel_launch(void* const* d_in, const int* in_sizes, int n_in,
                              void* d_out, int out_size) {
    const float* x   = (const float*)d_in[0];
    const int*   ei  = (const int*)d_in[1];
    const float* W1l = (const float*)d_in[2];
    const float* b1  = (const float*)d_in[3];
    const float* W1r = (const float*)d_in[4];
    const float* g1  = (const float*)d_in[5];
    const float* be1 = (const float*)d_in[6];
    const float* W2l = (const float*)d_in[7];
    const float* b2  = (const float*)d_in[8];
    const float* W2r = (const float*)d_in[9];
    const float* g2  = (const float*)d_in[10];
    const float* be2 = (const float*)d_in[11];
    float* out = (float*)d_out;

    const int n = in_sizes[0] / 64;
    const int E = in_sizes[1] / 2;

    void *aggp, *h1p, *statp, *degp, *rowp, *curp, *csrp, *bsump, *w2pp, *uvp;
    cudaGetSymbolAddress(&aggp, g_agg);
    cudaGetSymbolAddress(&h1p, g_h1);
    cudaGetSymbolAddress(&statp, g_stats);
    cudaGetSymbolAddress(&degp, g_degi);
    cudaGetSymbolAddress(&rowp, g_rowptr);
    cudaGetSymbolAddress(&curp, g_cur);
    cudaGetSymbolAddress(&csrp, g_csr);
    cudaGetSymbolAddress(&bsump, g_bsum);
    cudaGetSymbolAddress(&w2pp, g_w2p);
    cudaGetSymbolAddress(&uvp, g_uv);
    float* agg1   = (float*)aggp;
    float* agg2   = (float*)aggp + (size_t)MAXN * 64;
    float* h1     = (float*)h1p;
    float* stats1 = (float*)statp;
    float* stats2 = (float*)statp + 8192;
    int*   degi   = (int*)degp;
    int*   rowptr = (int*)rowp;
    int*   cur    = (int*)curp;
    int*   csr    = (int*)csrp;
    int*   bsum   = (int*)bsump;
    float* W2lp   = (float*)w2pp;
    float* W2rp   = (float*)w2pp + 16384;
    float* uv     = (float*)uvp;

    // SMEM: 128*WW2*8 + 2*128*20*8
    const int SMEM1 = 128 * 68 * 8  + 40960;   // 110592
    const int SMEM2 = 128 * 132 * 8 + 40960;   // 176128
    cudaFuncSetAttribute(sage_gemm_tc<128, false>,
                         cudaFuncAttributeMaxDynamicSharedMemorySize, SMEM1);
    cudaFuncSetAttribute(sage_gemm_tc<256, true>,
                         cudaFuncAttributeMaxDynamicSharedMemorySize, SMEM2);

    const int ntiles = (n + 127) / 128;
    const int nsb = (n + 255) / 256;
    const int gblocks = (n * 32 + 255) / 256;

    cudaMemsetAsync(degp, 0, (size_t)n * sizeof(int));
    cudaMemsetAsync(statp, 0, 16384 * sizeof(float));
    cudaMemsetAsync(uvp, 0, 256 * sizeof(float));

    // ---------------- CSR build ----------------
    csr_hist<<<(E + 255) / 256, 256>>>(ei, E, degi);
    scanA<<<nsb, 256>>>(degi, n, cur, bsum);
    scanB<<<1, 1024>>>(bsum, nsb);
    scanC<<<nsb, 256>>>(cur, bsum, n, E, rowptr, cur);
    csr_fill<<<(E + 255) / 256, 256>>>(ei, E, cur, csr);

    // ---------------- Layer 1 ----------------
    sage_gather<64><<<gblocks, 256>>>(x, rowptr, csr, agg1, n, 0);
    sage_gather<64><<<gblocks, 256>>>(x, rowptr, csr, agg1, n, 32);
    sage_gemm_tc<128, false><<<148, 512, SMEM1>>>(agg1, x, W1l, W1r, b1,
                                                  uv, degi, h1, stats1, n, ntiles);
    bn_finalize<<<1, 128>>>(g1, be1, stats1, 1.0f / (float)n);
    prep_layer2<<<16, 256>>>(W2l, W2r, W2lp, W2rp, uv);

    // ---------------- Layer 2 ----------------
    sage_gather<128><<<gblocks, 256>>>(h1, rowptr, csr, agg2, n, 0);
    sage_gather<128><<<gblocks, 256>>>(h1, rowptr, csr, agg2, n, 64);
    sage_gemm_tc<256, true><<<148, 512, SMEM2>>>(agg2, h1, W2lp, W2rp, b2,
                                                 uv, degi, out, stats2, n, ntiles);
    bn_finalize<<<1, 128>>>(g2, be2, stats2, 1.0f / (float)n);
    bn_apply_relu<<<((n * 32) + 255) / 256, 256>>>(out, n * 32);
}

// round 13
// speedup vs baseline: 1.1007x; 1.1007x over previous
#include <cuda_runtime.h>
#include <cuda_bf16.h>
#include <cstdint>

#define MAXN 200704
#define MAXE 1250048
__device__ float g_agg[(size_t)MAXN * 192];
__device__ float g_h1[(size_t)MAXN * 128];
__device__ int   g_degi[MAXN];
__device__ int   g_rowptr[MAXN + 8];
__device__ int   g_cur[MAXN];
__device__ int   g_csr[MAXE];
__device__ int   g_bsum[1032];
__device__ float g_w2p[32768];     // folded W2l' then W2r'
__device__ float g_uv[256];        // u = t@W2l ; v = t@W2r
__device__ float g_stats[16384];   // layer L at L*8192: [sum 128x32][sq 128x32]
__device__ float g_scale[128];
__device__ float g_shift[128];

// ---------------------------------------------------------------------------
__device__ __forceinline__ void red_add1(float* p, float v) {
    asm volatile("red.global.add.f32 [%0], %1;" :: "l"(p), "f"(v) : "memory");
}
__device__ __forceinline__ void mma_bf16(float* d, const uint32_t* a,
                                         uint32_t b0, uint32_t b1) {
    asm volatile("mma.sync.aligned.m16n8k16.row.col.f32.bf16.bf16.f32 "
                 "{%0,%1,%2,%3},{%4,%5,%6,%7},{%8,%9},{%0,%1,%2,%3};"
                 : "+f"(d[0]), "+f"(d[1]), "+f"(d[2]), "+f"(d[3])
                 : "r"(a[0]), "r"(a[1]), "r"(a[2]), "r"(a[3]),
                   "r"(b0), "r"(b1));
}
// split (x,y) into packed bf16 hi pair (ret) and lo pair (out param)
__device__ __forceinline__ uint32_t bfsplit2(float x, float y, uint32_t& lo2) {
    __nv_bfloat16 hx = __float2bfloat16(x);
    __nv_bfloat16 hy = __float2bfloat16(y);
    __nv_bfloat16 lx = __float2bfloat16(x - __bfloat162float(hx));
    __nv_bfloat16 ly = __float2bfloat16(y - __bfloat162float(hy));
    lo2 = (uint32_t)__bfloat16_as_ushort(lx) | ((uint32_t)__bfloat16_as_ushort(ly) << 16);
    return (uint32_t)__bfloat16_as_ushort(hx) | ((uint32_t)__bfloat16_as_ushort(hy) << 16);
}

// ---------------------------------------------------------------------------
// CSR build: histogram -> 3-step exclusive scan -> bucket fill
// ---------------------------------------------------------------------------
__global__ void csr_hist(const int* __restrict__ ei, int E, int* __restrict__ degi) {
    int e = blockIdx.x * blockDim.x + threadIdx.x;
    if (e >= E) return;
    atomicAdd(&degi[ei[E + e]], 1);
}
__global__ void scanA(const int* __restrict__ degi, int n,
                      int* __restrict__ locex, int* __restrict__ bsum) {
    int i = blockIdx.x * 256 + threadIdx.x;
    int v = (i < n) ? degi[i] : 0;
    int lane = threadIdx.x & 31, w = threadIdx.x >> 5;
    int x = v;
#pragma unroll
    for (int o = 1; o < 32; o <<= 1) {
        int t = __shfl_up_sync(0xFFFFFFFFu, x, o);
        if (lane >= o) x += t;
    }
    __shared__ int ws[8], wp[8];
    if (lane == 31) ws[w] = x;
    __syncthreads();
    if (threadIdx.x == 0) {
        int run = 0;
#pragma unroll
        for (int j = 0; j < 8; j++) { wp[j] = run; run += ws[j]; }
        bsum[blockIdx.x] = run;
    }
    __syncthreads();
    if (i < MAXN) locex[i] = x - v + wp[w];
}
__global__ void scanB(int* __restrict__ bsum, int nb) {
    __shared__ int s[1024];
    int t = threadIdx.x;
    int v = (t < nb) ? bsum[t] : 0;
    s[t] = v;
    __syncthreads();
    for (int o = 1; o < 1024; o <<= 1) {
        int add = (t >= o) ? s[t - o] : 0;
        __syncthreads();
        s[t] += add;
        __syncthreads();
    }
    if (t < nb) bsum[t] = s[t] - v;
}
__global__ void scanC(const int* __restrict__ locex, const int* __restrict__ bsum,
                      int n, int E, int* __restrict__ rowptr, int* __restrict__ cur) {
    int i = blockIdx.x * 256 + threadIdx.x;
    if (i < n) {
        int r = locex[i] + bsum[blockIdx.x];
        rowptr[i] = r;
        cur[i] = r;
    }
    if (i == 0) rowptr[n] = E;
}
__global__ void csr_fill(const int* __restrict__ ei, int E,
                         int* __restrict__ cur, int* __restrict__ csr) {
    int e = blockIdx.x * blockDim.x + threadIdx.x;
    if (e >= E) return;
    int s = ei[e], d = ei[E + e];
    int pos = atomicAdd(&cur[d], 1);
    csr[pos] = s;
}

// ---------------------------------------------------------------------------
// Gather aggregation: one warp per dst node, SPAN features starting at f_lo.
// ---------------------------------------------------------------------------
template <int F, int SPAN>
__global__ void sage_gather(const float* __restrict__ feat,
                            const int* __restrict__ rowptr,
                            const int* __restrict__ csr,
                            float* __restrict__ agg, int n, int f_lo) {
    constexpr int LPE = SPAN / 4;    // lanes per edge
    constexpr int EP  = 32 / LPE;    // edges in parallel
    int gw = (blockIdx.x * blockDim.x + threadIdx.x) >> 5;
    if (gw >= n) return;
    int lane  = threadIdx.x & 31;
    int eslot = lane / LPE;
    int fo    = f_lo + (lane % LPE) * 4;
    int b = rowptr[gw], e = rowptr[gw + 1];
    float4 acc = make_float4(0.f, 0.f, 0.f, 0.f);
    for (int i = b + eslot; i < e; i += EP) {
        int s = csr[i];
        float4 v = *(const float4*)(feat + (size_t)s * F + fo);
        acc.x += v.x; acc.y += v.y; acc.z += v.z; acc.w += v.w;
    }
#pragma unroll
    for (int o = LPE; o < 32; o <<= 1) {
        acc.x += __shfl_down_sync(0xFFFFFFFFu, acc.x, o);
        acc.y += __shfl_down_sync(0xFFFFFFFFu, acc.y, o);
        acc.z += __shfl_down_sync(0xFFFFFFFFu, acc.z, o);
        acc.w += __shfl_down_sync(0xFFFFFFFFu, acc.w, o);
    }
    if (eslot == 0)
        *(float4*)(agg + (size_t)gw * F + fo) = acc;
}

// Fold BN1 into layer-2 weights
__global__ void prep_layer2(const float* __restrict__ W2l,
                            const float* __restrict__ W2r,
                            float* __restrict__ W2lp, float* __restrict__ W2rp,
                            float* __restrict__ uv) {
    int nidx = threadIdx.x & 127;
    int ko   = threadIdx.x >> 7;
    int kb   = blockIdx.x * 8;
    float usum = 0.f, vsum = 0.f;
#pragma unroll
    for (int i = 0; i < 4; i++) {
        int k = kb + i * 2 + ko;
        float s = g_scale[k], t = g_shift[k];
        float wl = W2l[k * 128 + nidx];
        float wr = W2r[k * 128 + nidx];
        W2lp[k * 128 + nidx] = wl * s;
        W2rp[k * 128 + nidx] = wr * s;
        usum += t * wl;
        vsum += t * wr;
    }
    red_add1(&uv[nidx], usum);
    red_add1(&uv[128 + nidx], vsum);
}

// ---------------------------------------------------------------------------
// Persistent tensor-core dual GEMM: mma.sync m16n8k16 bf16, 3-term split.
// W stored FRAGMENT-MAJOR: sWf[(nb*KS16+ks)*32+lane] = {bh0,bh1,bl0,bl1}
// -> one LDS.128 per (ni,kstep). A = R11 layout: separate hi/lo arrays,
// rows padded to 20 words (bank 4g+t permutation), register-prefetch
// double buffer.
// ---------------------------------------------------------------------------
template <int K, bool DEG>
__global__ void __launch_bounds__(512, 1)
sage_gemm_tc(const float* __restrict__ A1,
             const float* __restrict__ A2,
             const float* __restrict__ Wl,
             const float* __restrict__ Wr,
             const float* __restrict__ bias,
             const float* __restrict__ uv,
             const int* __restrict__ degi,
             float* __restrict__ out, float* __restrict__ stats,
             int n, int ntiles) {
    extern __shared__ char smx[];
    constexpr int Kh   = K / 2;
    constexpr int NCH  = K / 32;             // 32-k chunks
    constexpr int KS16 = K / 16;             // k16 steps per tile
    constexpr int AW   = 128 * 20;           // words per A array (row stride 20)
    uint4*    sWf = (uint4*)smx;             // [16 nb][KS16 ks][32 lanes]
    uint32_t* sA  = (uint32_t*)(sWf + 16 * KS16 * 32);  // buf{0,1} x {hi,lo} x AW

    const int tid    = threadIdx.x;
    const int lane   = tid & 31;
    const int wid    = tid >> 5;
    const int warp_m = wid & 3;
    const int warp_n = wid >> 2;
    const int g      = lane >> 2;    // group 0..7
    const int t      = lane & 3;     // thread-in-group 0..3

    // ---- pack weights fragment-major (hi/lo pairs of B fragments) ----
    // pair index q in [0, K/2): q < Kh/2 -> Wl pair q ; else Wr pair q-Kh/2.
    for (int idx = tid; idx < 16 * KS16 * 32; idx += 512) {
        int fidx = idx >> 5, ln = idx & 31;
        int nb = fidx / KS16, ks = fidx % KS16;
        int gg = ln >> 2, tt = ln & 3;
        int nn = 8 * nb + gg;
        uint4 frag;
#pragma unroll
        for (int h = 0; h < 2; h++) {
            int q = 8 * ks + tt + 4 * h;
            float w0, w1;
            if (q < Kh / 2) {
                w0 = Wl[(2 * q) * 128 + nn];
                w1 = Wl[(2 * q + 1) * 128 + nn];
            } else {
                int qq = q - Kh / 2;
                w0 = Wr[(2 * qq) * 128 + nn];
                w1 = Wr[(2 * qq + 1) * 128 + nn];
            }
            uint32_t lo, hi = bfsplit2(w0, w1, lo);
            if (h == 0) { frag.x = hi; frag.z = lo; }
            else        { frag.y = hi; frag.w = lo; }
        }
        sWf[idx] = frag;
    }

    // epilogue constants: thread owns cols 32*warp_n + 8*ni + 2*t + j
    float bs[8], us[8];
#pragma unroll
    for (int ni = 0; ni < 4; ni++) {
#pragma unroll
        for (int j = 0; j < 2; j++) {
            int c = 32 * warp_n + 8 * ni + 2 * t + j;
            if (DEG) { bs[ni * 2 + j] = bias[c] + uv[128 + c]; us[ni * 2 + j] = uv[c]; }
            else     { bs[ni * 2 + j] = bias[c]; us[ni * 2 + j] = 0.f; }
        }
    }
    __syncthreads();

    // staging mapping: thread -> row tid>>2, k-seg (tid&3)*8 (8 floats = 4 pairs)
    const int srow = tid >> 2;
    const int sseg = (tid & 3) * 8;

    for (int tile = blockIdx.x; tile < ntiles; tile += gridDim.x) {
        const int row0 = tile << 7;

        // ---- stage chunk 0 ----
        {
            int gr = row0 + srow;
            float4 v0 = make_float4(0.f,0.f,0.f,0.f), v1 = v0;
            if (gr < n) {
                v0 = *(const float4*)(A1 + (size_t)gr * Kh + sseg);
                v1 = *(const float4*)(A1 + (size_t)gr * Kh + sseg + 4);
            }
            uint4 H, L;
            H.x = bfsplit2(v0.x, v0.y, L.x);
            H.y = bfsplit2(v0.z, v0.w, L.y);
            H.z = bfsplit2(v1.x, v1.y, L.z);
            H.w = bfsplit2(v1.z, v1.w, L.w);
            *(uint4*)(sA + srow * 20 + sseg / 2) = H;
            *(uint4*)(sA + AW + srow * 20 + sseg / 2) = L;
        }
        __syncthreads();

        float acc[2][4][4];
#pragma unroll
        for (int mi = 0; mi < 2; mi++)
#pragma unroll
            for (int ni = 0; ni < 4; ni++)
#pragma unroll
                for (int q = 0; q < 4; q++) acc[mi][ni][q] = 0.f;

        for (int c = 0; c < NCH; c++) {
            const int b = c & 1;
            float4 p0, p1;
            const bool havnext = (c + 1 < NCH);
            if (havnext) {
                const int kg0 = (c + 1) * 32;
                const float* src = (kg0 < Kh) ? A1 : A2;
                const int kof = kg0 & (Kh - 1);
                int gr = row0 + srow;
                p0 = make_float4(0.f,0.f,0.f,0.f); p1 = p0;
                if (gr < n) {
                    p0 = *(const float4*)(src + (size_t)gr * Kh + kof + sseg);
                    p1 = *(const float4*)(src + (size_t)gr * Kh + kof + sseg + 4);
                }
            }

            // ---- MMA over chunk c: 2 k16-steps ----
            uint32_t* sAb = sA + b * (2 * AW);
#pragma unroll
            for (int ks = 0; ks < 2; ks++) {
                const int ksg = c * 2 + ks;       // global kstep
                const int aw  = ks * 8;           // k-pair offset in A rows
                // B fragments: one LDS.128 per ni = {bh0,bh1,bl0,bl1}
                uint4 qb[4];
#pragma unroll
                for (int ni = 0; ni < 4; ni++) {
                    int nb = warp_n * 4 + ni;
                    qb[ni] = sWf[(nb * KS16 + ksg) * 32 + lane];
                }
#pragma unroll
                for (int mi = 0; mi < 2; mi++) {
                    const int rb = (32 * warp_m + 16 * mi + g) * 20 + aw + t;
                    uint32_t ah[4], al[4];
                    ah[0] = sAb[rb];                 al[0] = sAb[AW + rb];
                    ah[1] = sAb[rb + 8 * 20];        al[1] = sAb[AW + rb + 8 * 20];
                    ah[2] = sAb[rb + 4];             al[2] = sAb[AW + rb + 4];
                    ah[3] = sAb[rb + 8 * 20 + 4];    al[3] = sAb[AW + rb + 8 * 20 + 4];
#pragma unroll
                    for (int ni = 0; ni < 4; ni++) {
                        mma_bf16(acc[mi][ni], ah, qb[ni].x, qb[ni].y);
                        mma_bf16(acc[mi][ni], al, qb[ni].x, qb[ni].y);
                        mma_bf16(acc[mi][ni], ah, qb[ni].z, qb[ni].w);
                    }
                }
            }

            if (havnext) {
                const int bn = (c + 1) & 1;
                uint4 H, L;
                H.x = bfsplit2(p0.x, p0.y, L.x);
                H.y = bfsplit2(p0.z, p0.w, L.y);
                H.z = bfsplit2(p1.x, p1.y, L.z);
                H.w = bfsplit2(p1.z, p1.w, L.w);
                *(uint4*)(sA + bn * (2 * AW) + srow * 20 + sseg / 2) = H;
                *(uint4*)(sA + bn * (2 * AW) + AW + srow * 20 + sseg / 2) = L;
            }
            __syncthreads();
        }

        // ---- epilogue: bias(+deg*u), relu, store, BN stats ----
        float psum[8], psq[8];
#pragma unroll
        for (int q = 0; q < 8; q++) { psum[q] = 0.f; psq[q] = 0.f; }

#pragma unroll
        for (int mi = 0; mi < 2; mi++) {
#pragma unroll
            for (int half = 0; half < 2; half++) {
                int gr = row0 + 32 * warp_m + 16 * mi + g + 8 * half;
                if (gr >= n) continue;
                float dg = DEG ? (float)degi[gr] : 0.f;
#pragma unroll
                for (int ni = 0; ni < 4; ni++) {
                    int c0 = 32 * warp_n + 8 * ni + 2 * t;
                    float v0 = acc[mi][ni][2 * half]     + bs[ni * 2]     + dg * us[ni * 2];
                    float v1 = acc[mi][ni][2 * half + 1] + bs[ni * 2 + 1] + dg * us[ni * 2 + 1];
                    v0 = fmaxf(v0, 0.f);
                    v1 = fmaxf(v1, 0.f);
                    psum[ni * 2]     += v0;  psq[ni * 2]     += v0 * v0;
                    psum[ni * 2 + 1] += v1;  psq[ni * 2 + 1] += v1 * v1;
                    *(float2*)(out + (size_t)gr * 128 + c0) = make_float2(v0, v1);
                }
            }
        }
#pragma unroll
        for (int q = 0; q < 8; q++) {
#pragma unroll
            for (int o = 4; o < 32; o <<= 1) {
                psum[q] += __shfl_down_sync(0xFFFFFFFFu, psum[q], o);
                psq[q]  += __shfl_down_sync(0xFFFFFFFFu, psq[q], o);
            }
        }
        if (g == 0) {
            int slot = ((tile & 7) << 2) | warp_m;
#pragma unroll
            for (int q = 0; q < 8; q++) {
                int col = 32 * warp_n + 8 * (q >> 1) + 2 * t + (q & 1);
                red_add1(&stats[col * 32 + slot], psum[q]);
                red_add1(&stats[4096 + col * 32 + slot], psq[q]);
            }
        }
        __syncthreads();
    }
}

// ---------------------------------------------------------------------------
__global__ void bn_finalize(const float* __restrict__ gamma,
                            const float* __restrict__ beta,
                            const float* __restrict__ stats, float inv_n) {
    int c = threadIdx.x;
    float s = 0.f, q = 0.f;
#pragma unroll
    for (int j = 0; j < 32; j++) {
        s += stats[c * 32 + j];
        q += stats[4096 + c * 32 + j];
    }
    float mu  = s * inv_n;
    float var = q * inv_n - mu * mu;
    float sc  = gamma[c] * rsqrtf(var + 1e-5f);
    g_scale[c] = sc;
    g_shift[c] = beta[c] - mu * sc;
}

__global__ void bn_apply_relu(float* __restrict__ out, int total4) {
    int i = blockIdx.x * blockDim.x + threadIdx.x;
    if (i >= total4) return;
    float4 v = ((float4*)out)[i];
    int c = (i & 31) * 4;
    float4 sc = *(const float4*)(g_scale + c);
    float4 sh = *(const float4*)(g_shift + c);
    v.x = fmaxf(fmaf(v.x, sc.x, sh.x), 0.f);
    v.y = fmaxf(fmaf(v.y, sc.y, sh.y), 0.f);
    v.z = fmaxf(fmaf(v.z, sc.z, sh.z), 0.f);
    v.w = fmaxf(fmaf(v.w, sc.w, sh.w), 0.f);
    ((float4*)out)[i] = v;
}

// ---------------------------------------------------------------------------
extern "C" void kernel_launch(void* const* d_in, const int* in_sizes, int n_in,
                              void* d_out, int out_size) {
    const float* x   = (const float*)d_in[0];
    const int*   ei  = (const int*)d_in[1];
    const float* W1l = (const float*)d_in[2];
    const float* b1  = (const float*)d_in[3];
    const float* W1r = (const float*)d_in[4];
    const float* g1  = (const float*)d_in[5];
    const float* be1 = (const float*)d_in[6];
    const float* W2l = (const float*)d_in[7];
    const float* b2  = (const float*)d_in[8];
    const float* W2r = (const float*)d_in[9];
    const float* g2  = (const float*)d_in[10];
    const float* be2 = (const float*)d_in[11];
    float* out = (float*)d_out;

    const int n = in_sizes[0] / 64;
    const int E = in_sizes[1] / 2;

    void *aggp, *h1p, *statp, *degp, *rowp, *curp, *csrp, *bsump, *w2pp, *uvp;
    cudaGetSymbolAddress(&aggp, g_agg);
    cudaGetSymbolAddress(&h1p, g_h1);
    cudaGetSymbolAddress(&statp, g_stats);
    cudaGetSymbolAddress(&degp, g_degi);
    cudaGetSymbolAddress(&rowp, g_rowptr);
    cudaGetSymbolAddress(&curp, g_cur);
    cudaGetSymbolAddress(&csrp, g_csr);
    cudaGetSymbolAddress(&bsump, g_bsum);
    cudaGetSymbolAddress(&w2pp, g_w2p);
    cudaGetSymbolAddress(&uvp, g_uv);
    float* agg1   = (float*)aggp;
    float* agg2   = (float*)aggp + (size_t)MAXN * 64;
    float* h1     = (float*)h1p;
    float* stats1 = (float*)statp;
    float* stats2 = (float*)statp + 8192;
    int*   degi   = (int*)degp;
    int*   rowptr = (int*)rowp;
    int*   cur    = (int*)curp;
    int*   csr    = (int*)csrp;
    int*   bsum   = (int*)bsump;
    float* W2lp   = (float*)w2pp;
    float* W2rp   = (float*)w2pp + 16384;
    float* uv     = (float*)uvp;

    // SMEM: Wf (16*KS16*32*16 B) + A bufs (4*128*20*4 = 40960)
    const int SMEM1 = 16 * 8 * 32 * 16  + 40960;   // 106496
    const int SMEM2 = 16 * 16 * 32 * 16 + 40960;   // 172032
    cudaFuncSetAttribute(sage_gemm_tc<128, false>,
                         cudaFuncAttributeMaxDynamicSharedMemorySize, SMEM1);
    cudaFuncSetAttribute(sage_gemm_tc<256, true>,
                         cudaFuncAttributeMaxDynamicSharedMemorySize, SMEM2);

    const int ntiles = (n + 127) / 128;
    const int nsb = (n + 255) / 256;
    const int gblocks = (n * 32 + 255) / 256;

    cudaMemsetAsync(degp, 0, (size_t)n * sizeof(int));
    cudaMemsetAsync(statp, 0, 16384 * sizeof(float));
    cudaMemsetAsync(uvp, 0, 256 * sizeof(float));

    // ---------------- CSR build ----------------
    csr_hist<<<(E + 255) / 256, 256>>>(ei, E, degi);
    scanA<<<nsb, 256>>>(degi, n, cur, bsum);
    scanB<<<1, 1024>>>(bsum, nsb);
    scanC<<<nsb, 256>>>(cur, bsum, n, E, rowptr, cur);
    csr_fill<<<(E + 255) / 256, 256>>>(ei, E, cur, csr);

    // ---------------- Layer 1 ----------------
    sage_gather<64, 64><<<gblocks, 256>>>(x, rowptr, csr, agg1, n, 0);
    sage_gemm_tc<128, false><<<148, 512, SMEM1>>>(agg1, x, W1l, W1r, b1,
                                                  uv, degi, h1, stats1, n, ntiles);
    bn_finalize<<<1, 128>>>(g1, be1, stats1, 1.0f / (float)n);
    prep_layer2<<<16, 256>>>(W2l, W2r, W2lp, W2rp, uv);

    // ---------------- Layer 2 ----------------
    sage_gather<128, 64><<<gblocks, 256>>>(h1, rowptr, csr, agg2, n, 0);
    sage_gather<128, 64><<<gblocks, 256>>>(h1, rowptr, csr, agg2, n, 64);
    sage_gemm_tc<256, true><<<148, 512, SMEM2>>>(agg2, h1, W2lp, W2rp, b2,
                                                 uv, degi, out, stats2, n, ntiles);
    bn_finalize<<<1, 128>>>(g2, be2, stats2, 1.0f / (float)n);
    bn_apply_relu<<<((n * 32) + 255) / 256, 256>>>(out, n * 32);
}